// round 8
// baseline (speedup 1.0000x reference)
#include <cuda_runtime.h>

#define NROWS  65536
#define KCODES 1024
#define DDIM   256

#define TN 128          // rows per CTA tile
#define TK 128          // codes per K-chunk
#define DC 16           // D-slice per smem stage
#define NSTEPS (DDIM / DC)
#define TNP (TN + 4)    // smem padding to reduce bank conflicts (keeps 16B alignment)
#define TKP (TK + 4)

__device__ float  g_rowA[NROWS];   // ||x_n||^2
__device__ float  g_colB[KCODES];  // ||e_k||^2
__device__ int    g_idx[NROWS];
__device__ double g_part[1024];

// ---------------------------------------------------------------------------
// squared row norms: one warp per row (coalesced), fp32 fma + butterfly reduce
// which == 0 -> write g_rowA,  which == 1 -> write g_colB
// ---------------------------------------------------------------------------
__global__ void vq_sqnorm_kernel(const float* __restrict__ src, int nrows, int which)
{
    int gw   = (blockIdx.x * blockDim.x + threadIdx.x) >> 5;
    int lane = threadIdx.x & 31;
    if (gw >= nrows) return;
    const float* p = src + (size_t)gw * DDIM;
    float s = 0.f;
#pragma unroll
    for (int i = 0; i < DDIM / 32; ++i) {
        float v = p[i * 32 + lane];
        s = fmaf(v, v, s);
    }
#pragma unroll
    for (int m = 16; m > 0; m >>= 1)
        s += __shfl_xor_sync(0xffffffffu, s, m);
    if (lane == 0) {
        if (which == 0) g_rowA[gw] = s;
        else            g_colB[gw] = s;
    }
}

// ---------------------------------------------------------------------------
// fused GEMM + argmin:
//   dist[n,k] = round( round(A_n + b_k) - 2 * dot(x_n, e_k) )   (fp32, matches ref)
//   idx[n] = argmin_k dist  (tie -> smallest k, matches jnp.argmin)
// CTA: 256 threads as (tx=16 code-groups, ty=16 row-groups), 8x8 register tile.
// Tile: 128 rows x 128 codes, K-chunks of 128 over 1024 codes,
// D staged through double-buffered smem in slices of 16.
// ---------------------------------------------------------------------------
__global__ __launch_bounds__(256) void vq_argmin_kernel(
    const float* __restrict__ x, const float* __restrict__ emb)
{
    __shared__ __align__(16) float sx[2][DC][TNP];
    __shared__ __align__(16) float se[2][DC][TKP];

    const int tid = threadIdx.x;
    const int tx  = tid & 15;
    const int ty  = tid >> 4;
    const int r0  = blockIdx.x * TN;

    float rowA[8];
#pragma unroll
    for (int i = 0; i < 8; ++i) rowA[i] = g_rowA[r0 + ty * 8 + i];

    float bestv[8];
    int   besti[8];
#pragma unroll
    for (int i = 0; i < 8; ++i) { bestv[i] = 3.402823466e38f; besti[i] = 0; }

    float4 vx[2], ve[2];

#pragma unroll 1
    for (int kc = 0; kc < KCODES; kc += TK) {
        float acc[8][8];
#pragma unroll
        for (int i = 0; i < 8; ++i)
#pragma unroll
            for (int j = 0; j < 8; ++j) acc[i][j] = 0.f;

        // ---- load first D-slice ----
        {
            const int dbase = 0;
#pragma unroll
            for (int s = 0; s < 2; ++s) {
                int f = tid + s * 256;          // 0..511
                int row = f >> 2;               // 0..127
                int seg = f & 3;                // 4 floats each
                vx[s] = *(const float4*)(x   + (size_t)(r0 + row) * DDIM + dbase + seg * 4);
                ve[s] = *(const float4*)(emb + (size_t)(kc + row) * DDIM + dbase + seg * 4);
            }
        }
        __syncthreads();   // previous chunk's readers done before we overwrite smem
        int buf = 0;
#pragma unroll
        for (int s = 0; s < 2; ++s) {
            int f = tid + s * 256;
            int row = f >> 2, seg = f & 3;
            sx[buf][seg*4+0][row] = vx[s].x; sx[buf][seg*4+1][row] = vx[s].y;
            sx[buf][seg*4+2][row] = vx[s].z; sx[buf][seg*4+3][row] = vx[s].w;
            se[buf][seg*4+0][row] = ve[s].x; se[buf][seg*4+1][row] = ve[s].y;
            se[buf][seg*4+2][row] = ve[s].z; se[buf][seg*4+3][row] = ve[s].w;
        }

#pragma unroll 1
        for (int step = 0; step < NSTEPS; ++step) {
            __syncthreads();   // current smem buffer is fully populated

            if (step + 1 < NSTEPS) {             // prefetch next slice to regs
                int dbase = (step + 1) * DC;
#pragma unroll
                for (int s = 0; s < 2; ++s) {
                    int f = tid + s * 256;
                    int row = f >> 2, seg = f & 3;
                    vx[s] = *(const float4*)(x   + (size_t)(r0 + row) * DDIM + dbase + seg * 4);
                    ve[s] = *(const float4*)(emb + (size_t)(kc + row) * DDIM + dbase + seg * 4);
                }
            }

            // ---- compute on smem[buf] ----
#pragma unroll
            for (int dd = 0; dd < DC; ++dd) {
                float xf[8], ef[8];
                *(float4*)&xf[0] = *(const float4*)&sx[buf][dd][ty * 8];
                *(float4*)&xf[4] = *(const float4*)&sx[buf][dd][ty * 8 + 4];
                *(float4*)&ef[0] = *(const float4*)&se[buf][dd][tx * 8];
                *(float4*)&ef[4] = *(const float4*)&se[buf][dd][tx * 8 + 4];
#pragma unroll
                for (int i = 0; i < 8; ++i)
#pragma unroll
                    for (int j = 0; j < 8; ++j)
                        acc[i][j] = fmaf(xf[i], ef[j], acc[i][j]);
            }

            if (step + 1 < NSTEPS) {
                __syncthreads();                 // everyone done reading buf^1's old data
                int nb = buf ^ 1;
#pragma unroll
                for (int s = 0; s < 2; ++s) {
                    int f = tid + s * 256;
                    int row = f >> 2, seg = f & 3;
                    sx[nb][seg*4+0][row] = vx[s].x; sx[nb][seg*4+1][row] = vx[s].y;
                    sx[nb][seg*4+2][row] = vx[s].z; sx[nb][seg*4+3][row] = vx[s].w;
                    se[nb][seg*4+0][row] = ve[s].x; se[nb][seg*4+1][row] = ve[s].y;
                    se[nb][seg*4+2][row] = ve[s].z; se[nb][seg*4+3][row] = ve[s].w;
                }
                buf = nb;
            }
        }

        // ---- epilogue for this K-chunk (replicates reference fp32 rounding) ----
        float bB[8];
        *(float4*)&bB[0] = *(const float4*)&g_colB[kc + tx * 8];
        *(float4*)&bB[4] = *(const float4*)&g_colB[kc + tx * 8 + 4];
#pragma unroll
        for (int i = 0; i < 8; ++i) {
#pragma unroll
            for (int j = 0; j < 8; ++j) {
                float t1   = rowA[i] + bB[j];            // round(A + b) -- the delta grid
                float dist = fmaf(-2.f, acc[i][j], t1);  // == round(t1 - 2*dot), 2*dot exact
                if (dist < bestv[i]) { bestv[i] = dist; besti[i] = kc + tx * 8 + j; }
            }
        }
    }

    // cross-thread argmin over the 16 tx lanes (same warp, 16-lane groups)
#pragma unroll
    for (int i = 0; i < 8; ++i) {
        float v  = bestv[i];
        int   bi = besti[i];
#pragma unroll
        for (int m = 8; m > 0; m >>= 1) {
            float ov = __shfl_xor_sync(0xffffffffu, v,  m);
            int   oi = __shfl_xor_sync(0xffffffffu, bi, m);
            if (ov < v || (ov == v && oi < bi)) { v = ov; bi = oi; }
        }
        if (tx == 0) g_idx[r0 + ty * 8 + i] = bi;
    }
}

// ---------------------------------------------------------------------------
// gather + straight-through output + per-block MSE partials (fp32 squares,
// double accumulation; deterministic).
// out[e] = x[e] + (emb[idx][e] - x[e])   (both roundings replicate reference)
// ---------------------------------------------------------------------------
__global__ void vq_gather_kernel(const float* __restrict__ x,
                                 const float* __restrict__ emb,
                                 float* __restrict__ out)
{
    __shared__ double sred[256];
    const float4* x4 = (const float4*)x;
    const float4* e4 = (const float4*)emb;
    float4*       o4 = (float4*)out;

    double s = 0.0;
    int base = blockIdx.x * 4096;               // 4096 float4 per block
#pragma unroll 4
    for (int it = 0; it < 16; ++it) {
        int f = base + it * 256 + threadIdx.x;
        int n = f >> 6;                          // 64 float4 per row
        int c = g_idx[n];
        float4 q  = e4[c * 64 + (f & 63)];
        float4 xv = x4[f];
        float t0 = q.x - xv.x, t1 = q.y - xv.y, t2 = q.z - xv.z, t3 = q.w - xv.w;
        float4 o = make_float4(xv.x + t0, xv.y + t1, xv.z + t2, xv.w + t3);
        o4[f] = o;
        s += (double)(t0 * t0) + (double)(t1 * t1) + (double)(t2 * t2) + (double)(t3 * t3);
    }
    sred[threadIdx.x] = s;
    __syncthreads();
#pragma unroll
    for (int m = 128; m > 0; m >>= 1) {
        if (threadIdx.x < m) sred[threadIdx.x] += sred[threadIdx.x + m];
        __syncthreads();
    }
    if (threadIdx.x == 0) g_part[blockIdx.x] = sred[0];
}

// loss = m + 0.25*m  with m = mean((q - x)^2); deterministic serial combine.
__global__ void vq_finalize_kernel(float* __restrict__ out, int write_loss)
{
    if (threadIdx.x == 0 && blockIdx.x == 0) {
        double s = 0.0;
        for (int i = 0; i < 1024; ++i) s += g_part[i];
        float m = (float)(s / ((double)NROWS * (double)DDIM));
        if (write_loss) out[(size_t)NROWS * DDIM] = m + 0.25f * m;
    }
}

// ---------------------------------------------------------------------------
extern "C" void kernel_launch(void* const* d_in, const int* in_sizes, int n_in,
                              void* d_out, int out_size)
{
    const float* x   = (const float*)d_in[0];
    const float* emb = (const float*)d_in[1];
    // defensive: if metadata order is swapped, fix it by size
    if (n_in >= 2 && in_sizes[0] == KCODES * DDIM && in_sizes[1] == NROWS * DDIM) {
        const float* t = x; x = emb; emb = t;
    }
    float* out = (float*)d_out;

    vq_sqnorm_kernel<<<(NROWS * 32) / 256, 256>>>(x,   NROWS,  0);
    vq_sqnorm_kernel<<<(KCODES * 32) / 256, 256>>>(emb, KCODES, 1);
    vq_argmin_kernel<<<NROWS / TN, 256>>>(x, emb);
    vq_gather_kernel<<<1024, 256>>>(x, emb, out);
    vq_finalize_kernel<<<1, 32>>>(out, out_size > NROWS * DDIM ? 1 : 0);
}

// round 9
// speedup vs baseline: 1.3761x; 1.3761x over previous
#include <cuda_runtime.h>
#include <cuda_bf16.h>

#define NROWS  65536
#define KCODES 1024
#define DDIM   256

// ---- stage-1 (tensor) tiling ----
#define MT   128          // rows per CTA
#define NC_  128          // codes per chunk (8 chunks of 128 = 1024)
#define KP   264          // padded smem row stride in bf16 elems (+16B -> conflict-free ldmatrix)
#define CAND_CAP 32
#define T_MARGIN 8e-3f    // >= 2 * worst-case bf16 distance error (~2.2e-3)

#define SM1_XS_BYTES   (MT * KP * 2)
#define SM1_ES_BYTES   (NC_ * KP * 2)
#define SM1_BYTES      (SM1_XS_BYTES + SM1_ES_BYTES + 128*4 + 128*4 + 128*CAND_CAP*2)

__device__ float          g_rowA[NROWS];            // ||x_n||^2 (fp32, exact)
__device__ float          g_colB[KCODES];           // ||e_k||^2
__device__ int            g_idx[NROWS];
__device__ int            g_cnt[NROWS];
__device__ unsigned short g_cand[NROWS * CAND_CAP];
__device__ double         g_part[2048];

static __device__ __forceinline__ unsigned smem_u32(const void* p) {
    return (unsigned)__cvta_generic_to_shared(p);
}
static __device__ __forceinline__ unsigned pack_bf16x2(float a, float b) {
    __nv_bfloat162 h = __floats2bfloat162_rn(a, b);
    return *reinterpret_cast<unsigned*>(&h);
}
static __device__ __forceinline__ void ldsm_x4(unsigned& r0, unsigned& r1,
                                               unsigned& r2, unsigned& r3, unsigned addr) {
    asm volatile("ldmatrix.sync.aligned.m8n8.x4.shared.b16 {%0,%1,%2,%3}, [%4];"
                 : "=r"(r0), "=r"(r1), "=r"(r2), "=r"(r3) : "r"(addr));
}
static __device__ __forceinline__ void mma16816(float* c, const unsigned* a,
                                                unsigned b0, unsigned b1) {
    asm volatile("mma.sync.aligned.m16n8k16.row.col.f32.bf16.bf16.f32 "
                 "{%0,%1,%2,%3}, {%4,%5,%6,%7}, {%8,%9}, {%0,%1,%2,%3};"
                 : "+f"(c[0]), "+f"(c[1]), "+f"(c[2]), "+f"(c[3])
                 : "r"(a[0]), "r"(a[1]), "r"(a[2]), "r"(a[3]), "r"(b0), "r"(b1));
}

// ---------------------------------------------------------------------------
// squared row norms (exact fp32, same as passing kernel)
// ---------------------------------------------------------------------------
__global__ void vq_sqnorm_kernel(const float* __restrict__ src, int nrows, int which)
{
    int gw   = (blockIdx.x * blockDim.x + threadIdx.x) >> 5;
    int lane = threadIdx.x & 31;
    if (gw >= nrows) return;
    const float* p = src + (size_t)gw * DDIM;
    float s = 0.f;
#pragma unroll
    for (int i = 0; i < DDIM / 32; ++i) { float v = p[i * 32 + lane]; s = fmaf(v, v, s); }
#pragma unroll
    for (int m = 16; m > 0; m >>= 1) s += __shfl_xor_sync(0xffffffffu, s, m);
    if (lane == 0) { if (which == 0) g_rowA[gw] = s; else g_colB[gw] = s; }
}

// ---------------------------------------------------------------------------
// Stage 1: bf16 tensor-core approximate distances + candidate collection.
// CTA = 128 rows x all 1024 codes (8 chunks of 128). 8 warps, each 64x32.
// Running per-row min in smem (atomicMin on positive-float-as-int), collect
// codes with dist_approx <= running_min + T (superset of true candidates).
// ---------------------------------------------------------------------------
__global__ __launch_bounds__(256, 1) void vq_stage1(
    const float* __restrict__ x, const float* __restrict__ emb)
{
    extern __shared__ __align__(16) char sm_raw[];
    __nv_bfloat16* xs = (__nv_bfloat16*)sm_raw;                          // [128][KP]
    __nv_bfloat16* es = (__nv_bfloat16*)(sm_raw + SM1_XS_BYTES);         // [128][KP]
    int*            s_min  = (int*)(sm_raw + SM1_XS_BYTES + SM1_ES_BYTES);
    int*            s_cnt  = s_min + 128;
    unsigned short* s_cand = (unsigned short*)(s_cnt + 128);             // [128][32]

    const int tid = threadIdx.x, lane = tid & 31, wid = tid >> 5;
    const int warp_m = (wid & 1) * 64, warp_n = (wid >> 1) * 32;
    const int g  = lane >> 2;          // 0..7
    const int t4 = lane & 3;           // 0..3
    const int r0 = blockIdx.x * MT;

    if (tid < 128) { s_min[tid] = 0x7f800000; s_cnt[tid] = 0; }

    // load + convert x tile to bf16 smem
    for (int i = tid; i < MT * 64; i += 256) {
        int row = i >> 6, dp = i & 63;
        float4 v = ((const float4*)x)[(size_t)(r0 + row) * 64 + dp];
        uint2 p; p.x = pack_bf16x2(v.x, v.y); p.y = pack_bf16x2(v.z, v.w);
        *(uint2*)&xs[row * KP + dp * 4] = p;
    }

    float rA[4][2];
#pragma unroll
    for (int mf = 0; mf < 4; ++mf) {
        rA[mf][0] = g_rowA[r0 + warp_m + mf * 16 + g];
        rA[mf][1] = g_rowA[r0 + warp_m + mf * 16 + 8 + g];
    }

    // ldmatrix per-lane offsets: lane L supplies addr of matrix (L>>3), row (L&7)
    const int mA = lane >> 3, rL = lane & 7;
    const int a_row = (mA & 1) * 8 + rL, a_col = (mA >> 1) * 8;   // A: m0 r0-7/k0-7, m1 r8-15/k0-7, m2 r0-7/k8-15, m3 r8-15/k8-15
    const int b_row = (mA >> 1) * 8 + rL, b_col = (mA & 1) * 8;   // B: m0 n0-7/k0-7, m1 n0-7/k8-15, m2 n8-15/k0-7, m3 n8-15/k8-15

    const unsigned xs_b = smem_u32(xs), es_b = smem_u32(es);
    unsigned a_base[4];
#pragma unroll
    for (int mf = 0; mf < 4; ++mf)
        a_base[mf] = xs_b + (unsigned)(((warp_m + mf * 16 + a_row) * KP + a_col) * 2);
    unsigned b_base[2];
#pragma unroll
    for (int p = 0; p < 2; ++p)
        b_base[p] = es_b + (unsigned)(((warp_n + p * 16 + b_row) * KP + b_col) * 2);

#pragma unroll 1
    for (int nc = 0; nc < 8; ++nc) {
        // load + convert e chunk
        for (int i = tid; i < NC_ * 64; i += 256) {
            int row = i >> 6, dp = i & 63;
            float4 v = ((const float4*)emb)[(size_t)(nc * 128 + row) * 64 + dp];
            uint2 p; p.x = pack_bf16x2(v.x, v.y); p.y = pack_bf16x2(v.z, v.w);
            *(uint2*)&es[row * KP + dp * 4] = p;
        }
        __syncthreads();

        float acc[4][4][4];
#pragma unroll
        for (int i = 0; i < 4; ++i)
#pragma unroll
            for (int j = 0; j < 4; ++j)
#pragma unroll
                for (int k = 0; k < 4; ++k) acc[i][j][k] = 0.f;

#pragma unroll 4
        for (int kk = 0; kk < DDIM; kk += 16) {
            unsigned a[4][4], b[2][4];
#pragma unroll
            for (int mf = 0; mf < 4; ++mf)
                ldsm_x4(a[mf][0], a[mf][1], a[mf][2], a[mf][3], a_base[mf] + kk * 2);
#pragma unroll
            for (int p = 0; p < 2; ++p)
                ldsm_x4(b[p][0], b[p][1], b[p][2], b[p][3], b_base[p] + kk * 2);
#pragma unroll
            for (int mf = 0; mf < 4; ++mf)
#pragma unroll
                for (int nf = 0; nf < 4; ++nf)
                    mma16816(acc[mf][nf], a[mf],
                             b[nf >> 1][(nf & 1) * 2], b[nf >> 1][(nf & 1) * 2 + 1]);
        }

        // epilogue: dist = (A + b) - 2*dot; per-row running min
        float lmin[4][2];
#pragma unroll
        for (int mf = 0; mf < 4; ++mf) { lmin[mf][0] = 3.4e38f; lmin[mf][1] = 3.4e38f; }
#pragma unroll
        for (int mf = 0; mf < 4; ++mf)
#pragma unroll
            for (int nf = 0; nf < 4; ++nf) {
                int C0 = nc * 128 + warp_n + nf * 8 + t4 * 2;
                float cb0 = g_colB[C0], cb1 = g_colB[C0 + 1];
                float d0 = fmaf(-2.f, acc[mf][nf][0], rA[mf][0] + cb0);
                float d1 = fmaf(-2.f, acc[mf][nf][1], rA[mf][0] + cb1);
                float d2 = fmaf(-2.f, acc[mf][nf][2], rA[mf][1] + cb0);
                float d3 = fmaf(-2.f, acc[mf][nf][3], rA[mf][1] + cb1);
                acc[mf][nf][0] = d0; acc[mf][nf][1] = d1;
                acc[mf][nf][2] = d2; acc[mf][nf][3] = d3;
                lmin[mf][0] = fminf(lmin[mf][0], fminf(d0, d1));
                lmin[mf][1] = fminf(lmin[mf][1], fminf(d2, d3));
            }
#pragma unroll
        for (int mf = 0; mf < 4; ++mf) {
            atomicMin(&s_min[warp_m + mf * 16 + g],     __float_as_int(lmin[mf][0]));
            atomicMin(&s_min[warp_m + mf * 16 + 8 + g], __float_as_int(lmin[mf][1]));
        }
        __syncthreads();

        // collect candidates within margin of running min
#pragma unroll
        for (int mf = 0; mf < 4; ++mf) {
            int row0 = warp_m + mf * 16 + g, row1 = row0 + 8;
            float th0 = __int_as_float(s_min[row0]) + T_MARGIN;
            float th1 = __int_as_float(s_min[row1]) + T_MARGIN;
#pragma unroll
            for (int nf = 0; nf < 4; ++nf) {
                int C0 = nc * 128 + warp_n + nf * 8 + t4 * 2;
                if (acc[mf][nf][0] <= th0) { int p = atomicAdd(&s_cnt[row0], 1); if (p < CAND_CAP) s_cand[row0 * CAND_CAP + p] = (unsigned short)C0; }
                if (acc[mf][nf][1] <= th0) { int p = atomicAdd(&s_cnt[row0], 1); if (p < CAND_CAP) s_cand[row0 * CAND_CAP + p] = (unsigned short)(C0 + 1); }
                if (acc[mf][nf][2] <= th1) { int p = atomicAdd(&s_cnt[row1], 1); if (p < CAND_CAP) s_cand[row1 * CAND_CAP + p] = (unsigned short)C0; }
                if (acc[mf][nf][3] <= th1) { int p = atomicAdd(&s_cnt[row1], 1); if (p < CAND_CAP) s_cand[row1 * CAND_CAP + p] = (unsigned short)(C0 + 1); }
            }
        }
        __syncthreads();
    }

    for (int r = tid; r < 128; r += 256) {
        g_cnt[r0 + r] = s_cnt[r];
        const uint4* src = (const uint4*)&s_cand[r * CAND_CAP];
        uint4* dst = (uint4*)&g_cand[(size_t)(r0 + r) * CAND_CAP];
        dst[0] = src[0]; dst[1] = src[1]; dst[2] = src[2]; dst[3] = src[3];
    }
}

// ---------------------------------------------------------------------------
// Stage 2: exact refine. One warp per row, one lane per candidate.
// Serial fp32 fmaf chain d=0..255 + fmaf(-2,dot,A+b): bitwise identical to the
// previous passing kernel's distances -> identical argmin. Tie -> smallest idx.
// ---------------------------------------------------------------------------
__global__ __launch_bounds__(256) void vq_refine(
    const float* __restrict__ x, const float* __restrict__ emb)
{
    __shared__ float sx[8][260];
    const int wid = threadIdx.x >> 5, lane = threadIdx.x & 31;
    const int row = blockIdx.x * 8 + wid;

    const float4* xr = (const float4*)(x + (size_t)row * DDIM);
    ((float4*)&sx[wid][0])[lane]      = xr[lane];
    ((float4*)&sx[wid][0])[lane + 32] = xr[lane + 32];
    __syncwarp();

    const float A = g_rowA[row];
    const int cnt = g_cnt[row];
    const float4* xs4 = (const float4*)&sx[wid][0];

    float best; int bi;
    if (cnt <= CAND_CAP) {
        int c = g_cand[(size_t)row * CAND_CAP + (lane < cnt ? lane : cnt - 1)];
        float s = 0.f;
        const float4* e4 = (const float4*)(emb + (size_t)c * DDIM);
#pragma unroll 8
        for (int i = 0; i < 64; ++i) {
            float4 ev = e4[i];
            float4 xv = xs4[i];
            s = fmaf(xv.x, ev.x, s); s = fmaf(xv.y, ev.y, s);
            s = fmaf(xv.z, ev.z, s); s = fmaf(xv.w, ev.w, s);
        }
        float t1 = A + g_colB[c];
        best = fmaf(-2.f, s, t1);
        bi = c;
    } else {
        best = 3.4e38f; bi = 0;
        for (int c = lane; c < KCODES; c += 32) {
            float s = 0.f;
            const float4* e4 = (const float4*)(emb + (size_t)c * DDIM);
#pragma unroll 8
            for (int i = 0; i < 64; ++i) {
                float4 ev = e4[i];
                float4 xv = xs4[i];
                s = fmaf(xv.x, ev.x, s); s = fmaf(xv.y, ev.y, s);
                s = fmaf(xv.z, ev.z, s); s = fmaf(xv.w, ev.w, s);
            }
            float d = fmaf(-2.f, s, A + g_colB[c]);
            if (d < best) { best = d; bi = c; }   // ascending c keeps smallest index on ties
        }
    }
#pragma unroll
    for (int m = 16; m > 0; m >>= 1) {
        float ov = __shfl_xor_sync(0xffffffffu, best, m);
        int   oi = __shfl_xor_sync(0xffffffffu, bi,   m);
        if (ov < best || (ov == best && oi < bi)) { best = ov; bi = oi; }
    }
    if (lane == 0) g_idx[row] = bi;
}

// ---------------------------------------------------------------------------
// gather + straight-through output + per-block MSE partials
// ---------------------------------------------------------------------------
__global__ void vq_gather_kernel(const float* __restrict__ x,
                                 const float* __restrict__ emb,
                                 float* __restrict__ out)
{
    __shared__ double sred[256];
    const float4* x4 = (const float4*)x;
    const float4* e4 = (const float4*)emb;
    float4*       o4 = (float4*)out;

    double s = 0.0;
    int base = blockIdx.x * 2048;               // 2048 float4 per block
#pragma unroll 4
    for (int it = 0; it < 8; ++it) {
        int f = base + it * 256 + threadIdx.x;
        int n = f >> 6;
        int c = g_idx[n];
        float4 q  = e4[c * 64 + (f & 63)];
        float4 xv = x4[f];
        float t0 = q.x - xv.x, t1 = q.y - xv.y, t2 = q.z - xv.z, t3 = q.w - xv.w;
        o4[f] = make_float4(xv.x + t0, xv.y + t1, xv.z + t2, xv.w + t3);
        s += (double)(t0 * t0) + (double)(t1 * t1) + (double)(t2 * t2) + (double)(t3 * t3);
    }
    sred[threadIdx.x] = s;
    __syncthreads();
#pragma unroll
    for (int m = 128; m > 0; m >>= 1) {
        if (threadIdx.x < m) sred[threadIdx.x] += sred[threadIdx.x + m];
        __syncthreads();
    }
    if (threadIdx.x == 0) g_part[blockIdx.x] = sred[0];
}

// deterministic parallel finalize: fixed-shape tree reduction in double
__global__ void vq_finalize_kernel(float* __restrict__ out, int write_loss)
{
    __shared__ double sred[256];
    double s = 0.0;
#pragma unroll
    for (int i = 0; i < 8; ++i) s += g_part[threadIdx.x + i * 256];
    sred[threadIdx.x] = s;
    __syncthreads();
#pragma unroll
    for (int m = 128; m > 0; m >>= 1) {
        if (threadIdx.x < m) sred[threadIdx.x] += sred[threadIdx.x + m];
        __syncthreads();
    }
    if (threadIdx.x == 0 && write_loss) {
        float mmean = (float)(sred[0] / ((double)NROWS * (double)DDIM));
        out[(size_t)NROWS * DDIM] = mmean + 0.25f * mmean;
    }
}

// ---------------------------------------------------------------------------
extern "C" void kernel_launch(void* const* d_in, const int* in_sizes, int n_in,
                              void* d_out, int out_size)
{
    const float* x   = (const float*)d_in[0];
    const float* emb = (const float*)d_in[1];
    if (n_in >= 2 && in_sizes[0] == KCODES * DDIM && in_sizes[1] == NROWS * DDIM) {
        const float* t = x; x = emb; emb = t;
    }
    float* out = (float*)d_out;

    cudaFuncSetAttribute(vq_stage1, cudaFuncAttributeMaxDynamicSharedMemorySize, SM1_BYTES);

    vq_sqnorm_kernel<<<(NROWS * 32) / 256, 256>>>(x,   NROWS,  0);
    vq_sqnorm_kernel<<<(KCODES * 32) / 256, 256>>>(emb, KCODES, 1);
    vq_stage1<<<NROWS / MT, 256, SM1_BYTES>>>(x, emb);
    vq_refine<<<NROWS / 8, 256>>>(x, emb);
    vq_gather_kernel<<<2048, 256>>>(x, emb, out);
    vq_finalize_kernel<<<1, 256>>>(out, out_size > NROWS * DDIM ? 1 : 0);
}

// round 10
// speedup vs baseline: 1.3766x; 1.0004x over previous
#include <cuda_runtime.h>
#include <cuda_bf16.h>

#define NROWS  65536
#define KCODES 1024
#define DDIM   256

// ---- stage-1 (tensor) tiling ----
#define MT   128          // rows per CTA
#define NC_  128          // codes per chunk (8 chunks of 128 = 1024)
#define KP   264          // padded smem row stride in bf16 elems (+16B -> conflict-free ldmatrix)
#define CAND_CAP 32
#define T_MARGIN 8e-3f    // >= 2 * worst-case bf16 distance error (~2.2e-3)

#define SM1_XS_BYTES   (MT * KP * 2)
#define SM1_ES_BYTES   (NC_ * KP * 2)
#define SM1_BYTES      (SM1_XS_BYTES + SM1_ES_BYTES + 128*4 + 128*4 + 128*CAND_CAP*2)

__device__ float          g_rowA[NROWS];            // ||x_n||^2 (fp32, exact)
__device__ float          g_colB[KCODES];           // ||e_k||^2
__device__ int            g_idx[NROWS];
__device__ int            g_cnt[NROWS];
__device__ unsigned short g_cand[NROWS * CAND_CAP];
__device__ double         g_part[2048];

static __device__ __forceinline__ unsigned smem_u32(const void* p) {
    return (unsigned)__cvta_generic_to_shared(p);
}
static __device__ __forceinline__ unsigned pack_bf16x2(float a, float b) {
    __nv_bfloat162 h = __floats2bfloat162_rn(a, b);
    return *reinterpret_cast<unsigned*>(&h);
}
static __device__ __forceinline__ void ldsm_x4(unsigned& r0, unsigned& r1,
                                               unsigned& r2, unsigned& r3, unsigned addr) {
    asm volatile("ldmatrix.sync.aligned.m8n8.x4.shared.b16 {%0,%1,%2,%3}, [%4];"
                 : "=r"(r0), "=r"(r1), "=r"(r2), "=r"(r3) : "r"(addr));
}
static __device__ __forceinline__ void mma16816(float* c, const unsigned* a,
                                                unsigned b0, unsigned b1) {
    asm volatile("mma.sync.aligned.m16n8k16.row.col.f32.bf16.bf16.f32 "
                 "{%0,%1,%2,%3}, {%4,%5,%6,%7}, {%8,%9}, {%0,%1,%2,%3};"
                 : "+f"(c[0]), "+f"(c[1]), "+f"(c[2]), "+f"(c[3])
                 : "r"(a[0]), "r"(a[1]), "r"(a[2]), "r"(a[3]), "r"(b0), "r"(b1));
}

// ---------------------------------------------------------------------------
// squared row norms (exact fp32, same as passing kernel)
// ---------------------------------------------------------------------------
__global__ void vq_sqnorm_kernel(const float* __restrict__ src, int nrows, int which)
{
    int gw   = (blockIdx.x * blockDim.x + threadIdx.x) >> 5;
    int lane = threadIdx.x & 31;
    if (gw >= nrows) return;
    const float* p = src + (size_t)gw * DDIM;
    float s = 0.f;
#pragma unroll
    for (int i = 0; i < DDIM / 32; ++i) { float v = p[i * 32 + lane]; s = fmaf(v, v, s); }
#pragma unroll
    for (int m = 16; m > 0; m >>= 1) s += __shfl_xor_sync(0xffffffffu, s, m);
    if (lane == 0) { if (which == 0) g_rowA[gw] = s; else g_colB[gw] = s; }
}

// ---------------------------------------------------------------------------
// Stage 1: bf16 tensor-core approximate distances + candidate collection.
// CTA = 128 rows x all 1024 codes (8 chunks of 128). 8 warps, each 64x32.
// Running per-row min in smem (atomicMin on positive-float-as-int), collect
// codes with dist_approx <= running_min + T (superset of true candidates).
// ---------------------------------------------------------------------------
__global__ __launch_bounds__(256, 1) void vq_stage1(
    const float* __restrict__ x, const float* __restrict__ emb)
{
    extern __shared__ __align__(16) char sm_raw[];
    __nv_bfloat16* xs = (__nv_bfloat16*)sm_raw;                          // [128][KP]
    __nv_bfloat16* es = (__nv_bfloat16*)(sm_raw + SM1_XS_BYTES);         // [128][KP]
    int*            s_min  = (int*)(sm_raw + SM1_XS_BYTES + SM1_ES_BYTES);
    int*            s_cnt  = s_min + 128;
    unsigned short* s_cand = (unsigned short*)(s_cnt + 128);             // [128][32]

    const int tid = threadIdx.x, lane = tid & 31, wid = tid >> 5;
    const int warp_m = (wid & 1) * 64, warp_n = (wid >> 1) * 32;
    const int g  = lane >> 2;          // 0..7
    const int t4 = lane & 3;           // 0..3
    const int r0 = blockIdx.x * MT;

    if (tid < 128) { s_min[tid] = 0x7f800000; s_cnt[tid] = 0; }

    // load + convert x tile to bf16 smem
    for (int i = tid; i < MT * 64; i += 256) {
        int row = i >> 6, dp = i & 63;
        float4 v = ((const float4*)x)[(size_t)(r0 + row) * 64 + dp];
        uint2 p; p.x = pack_bf16x2(v.x, v.y); p.y = pack_bf16x2(v.z, v.w);
        *(uint2*)&xs[row * KP + dp * 4] = p;
    }

    float rA[4][2];
#pragma unroll
    for (int mf = 0; mf < 4; ++mf) {
        rA[mf][0] = g_rowA[r0 + warp_m + mf * 16 + g];
        rA[mf][1] = g_rowA[r0 + warp_m + mf * 16 + 8 + g];
    }

    // ldmatrix per-lane offsets: lane L supplies addr of matrix (L>>3), row (L&7)
    const int mA = lane >> 3, rL = lane & 7;
    const int a_row = (mA & 1) * 8 + rL, a_col = (mA >> 1) * 8;   // A: m0 r0-7/k0-7, m1 r8-15/k0-7, m2 r0-7/k8-15, m3 r8-15/k8-15
    const int b_row = (mA >> 1) * 8 + rL, b_col = (mA & 1) * 8;   // B: m0 n0-7/k0-7, m1 n0-7/k8-15, m2 n8-15/k0-7, m3 n8-15/k8-15

    const unsigned xs_b = smem_u32(xs), es_b = smem_u32(es);
    unsigned a_base[4];
#pragma unroll
    for (int mf = 0; mf < 4; ++mf)
        a_base[mf] = xs_b + (unsigned)(((warp_m + mf * 16 + a_row) * KP + a_col) * 2);
    unsigned b_base[2];
#pragma unroll
    for (int p = 0; p < 2; ++p)
        b_base[p] = es_b + (unsigned)(((warp_n + p * 16 + b_row) * KP + b_col) * 2);

#pragma unroll 1
    for (int nc = 0; nc < 8; ++nc) {
        // load + convert e chunk
        for (int i = tid; i < NC_ * 64; i += 256) {
            int row = i >> 6, dp = i & 63;
            float4 v = ((const float4*)emb)[(size_t)(nc * 128 + row) * 64 + dp];
            uint2 p; p.x = pack_bf16x2(v.x, v.y); p.y = pack_bf16x2(v.z, v.w);
            *(uint2*)&es[row * KP + dp * 4] = p;
        }
        __syncthreads();

        float acc[4][4][4];
#pragma unroll
        for (int i = 0; i < 4; ++i)
#pragma unroll
            for (int j = 0; j < 4; ++j)
#pragma unroll
                for (int k = 0; k < 4; ++k) acc[i][j][k] = 0.f;

#pragma unroll 4
        for (int kk = 0; kk < DDIM; kk += 16) {
            unsigned a[4][4], b[2][4];
#pragma unroll
            for (int mf = 0; mf < 4; ++mf)
                ldsm_x4(a[mf][0], a[mf][1], a[mf][2], a[mf][3], a_base[mf] + kk * 2);
#pragma unroll
            for (int p = 0; p < 2; ++p)
                ldsm_x4(b[p][0], b[p][1], b[p][2], b[p][3], b_base[p] + kk * 2);
#pragma unroll
            for (int mf = 0; mf < 4; ++mf)
#pragma unroll
                for (int nf = 0; nf < 4; ++nf)
                    mma16816(acc[mf][nf], a[mf],
                             b[nf >> 1][(nf & 1) * 2], b[nf >> 1][(nf & 1) * 2 + 1]);
        }

        // epilogue: dist = (A + b) - 2*dot; per-row running min
        float lmin[4][2];
#pragma unroll
        for (int mf = 0; mf < 4; ++mf) { lmin[mf][0] = 3.4e38f; lmin[mf][1] = 3.4e38f; }
#pragma unroll
        for (int mf = 0; mf < 4; ++mf)
#pragma unroll
            for (int nf = 0; nf < 4; ++nf) {
                int C0 = nc * 128 + warp_n + nf * 8 + t4 * 2;
                float cb0 = g_colB[C0], cb1 = g_colB[C0 + 1];
                float d0 = fmaf(-2.f, acc[mf][nf][0], rA[mf][0] + cb0);
                float d1 = fmaf(-2.f, acc[mf][nf][1], rA[mf][0] + cb1);
                float d2 = fmaf(-2.f, acc[mf][nf][2], rA[mf][1] + cb0);
                float d3 = fmaf(-2.f, acc[mf][nf][3], rA[mf][1] + cb1);
                acc[mf][nf][0] = d0; acc[mf][nf][1] = d1;
                acc[mf][nf][2] = d2; acc[mf][nf][3] = d3;
                lmin[mf][0] = fminf(lmin[mf][0], fminf(d0, d1));
                lmin[mf][1] = fminf(lmin[mf][1], fminf(d2, d3));
            }
#pragma unroll
        for (int mf = 0; mf < 4; ++mf) {
            atomicMin(&s_min[warp_m + mf * 16 + g],     __float_as_int(lmin[mf][0]));
            atomicMin(&s_min[warp_m + mf * 16 + 8 + g], __float_as_int(lmin[mf][1]));
        }
        __syncthreads();

        // collect candidates within margin of running min
#pragma unroll
        for (int mf = 0; mf < 4; ++mf) {
            int row0 = warp_m + mf * 16 + g, row1 = row0 + 8;
            float th0 = __int_as_float(s_min[row0]) + T_MARGIN;
            float th1 = __int_as_float(s_min[row1]) + T_MARGIN;
#pragma unroll
            for (int nf = 0; nf < 4; ++nf) {
                int C0 = nc * 128 + warp_n + nf * 8 + t4 * 2;
                if (acc[mf][nf][0] <= th0) { int p = atomicAdd(&s_cnt[row0], 1); if (p < CAND_CAP) s_cand[row0 * CAND_CAP + p] = (unsigned short)C0; }
                if (acc[mf][nf][1] <= th0) { int p = atomicAdd(&s_cnt[row0], 1); if (p < CAND_CAP) s_cand[row0 * CAND_CAP + p] = (unsigned short)(C0 + 1); }
                if (acc[mf][nf][2] <= th1) { int p = atomicAdd(&s_cnt[row1], 1); if (p < CAND_CAP) s_cand[row1 * CAND_CAP + p] = (unsigned short)C0; }
                if (acc[mf][nf][3] <= th1) { int p = atomicAdd(&s_cnt[row1], 1); if (p < CAND_CAP) s_cand[row1 * CAND_CAP + p] = (unsigned short)(C0 + 1); }
            }
        }
        __syncthreads();
    }

    for (int r = tid; r < 128; r += 256) {
        g_cnt[r0 + r] = s_cnt[r];
        const uint4* src = (const uint4*)&s_cand[r * CAND_CAP];
        uint4* dst = (uint4*)&g_cand[(size_t)(r0 + r) * CAND_CAP];
        dst[0] = src[0]; dst[1] = src[1]; dst[2] = src[2]; dst[3] = src[3];
    }
}

// ---------------------------------------------------------------------------
// Stage 2: exact refine. One warp per row, one lane per candidate.
// Serial fp32 fmaf chain d=0..255 + fmaf(-2,dot,A+b): bitwise identical to the
// previous passing kernel's distances -> identical argmin. Tie -> smallest idx.
// ---------------------------------------------------------------------------
__global__ __launch_bounds__(256) void vq_refine(
    const float* __restrict__ x, const float* __restrict__ emb)
{
    __shared__ float sx[8][260];
    const int wid = threadIdx.x >> 5, lane = threadIdx.x & 31;
    const int row = blockIdx.x * 8 + wid;

    const float4* xr = (const float4*)(x + (size_t)row * DDIM);
    ((float4*)&sx[wid][0])[lane]      = xr[lane];
    ((float4*)&sx[wid][0])[lane + 32] = xr[lane + 32];
    __syncwarp();

    const float A = g_rowA[row];
    const int cnt = g_cnt[row];
    const float4* xs4 = (const float4*)&sx[wid][0];

    float best; int bi;
    if (cnt <= CAND_CAP) {
        int c = g_cand[(size_t)row * CAND_CAP + (lane < cnt ? lane : cnt - 1)];
        float s = 0.f;
        const float4* e4 = (const float4*)(emb + (size_t)c * DDIM);
#pragma unroll 8
        for (int i = 0; i < 64; ++i) {
            float4 ev = e4[i];
            float4 xv = xs4[i];
            s = fmaf(xv.x, ev.x, s); s = fmaf(xv.y, ev.y, s);
            s = fmaf(xv.z, ev.z, s); s = fmaf(xv.w, ev.w, s);
        }
        float t1 = A + g_colB[c];
        best = fmaf(-2.f, s, t1);
        bi = c;
    } else {
        best = 3.4e38f; bi = 0;
        for (int c = lane; c < KCODES; c += 32) {
            float s = 0.f;
            const float4* e4 = (const float4*)(emb + (size_t)c * DDIM);
#pragma unroll 8
            for (int i = 0; i < 64; ++i) {
                float4 ev = e4[i];
                float4 xv = xs4[i];
                s = fmaf(xv.x, ev.x, s); s = fmaf(xv.y, ev.y, s);
                s = fmaf(xv.z, ev.z, s); s = fmaf(xv.w, ev.w, s);
            }
            float d = fmaf(-2.f, s, A + g_colB[c]);
            if (d < best) { best = d; bi = c; }   // ascending c keeps smallest index on ties
        }
    }
#pragma unroll
    for (int m = 16; m > 0; m >>= 1) {
        float ov = __shfl_xor_sync(0xffffffffu, best, m);
        int   oi = __shfl_xor_sync(0xffffffffu, bi,   m);
        if (ov < best || (ov == best && oi < bi)) { best = ov; bi = oi; }
    }
    if (lane == 0) g_idx[row] = bi;
}

// ---------------------------------------------------------------------------
// gather + straight-through output + per-block MSE partials
// ---------------------------------------------------------------------------
__global__ void vq_gather_kernel(const float* __restrict__ x,
                                 const float* __restrict__ emb,
                                 float* __restrict__ out)
{
    __shared__ double sred[256];
    const float4* x4 = (const float4*)x;
    const float4* e4 = (const float4*)emb;
    float4*       o4 = (float4*)out;

    double s = 0.0;
    int base = blockIdx.x * 2048;               // 2048 float4 per block
#pragma unroll 4
    for (int it = 0; it < 8; ++it) {
        int f = base + it * 256 + threadIdx.x;
        int n = f >> 6;
        int c = g_idx[n];
        float4 q  = e4[c * 64 + (f & 63)];
        float4 xv = x4[f];
        float t0 = q.x - xv.x, t1 = q.y - xv.y, t2 = q.z - xv.z, t3 = q.w - xv.w;
        o4[f] = make_float4(xv.x + t0, xv.y + t1, xv.z + t2, xv.w + t3);
        s += (double)(t0 * t0) + (double)(t1 * t1) + (double)(t2 * t2) + (double)(t3 * t3);
    }
    sred[threadIdx.x] = s;
    __syncthreads();
#pragma unroll
    for (int m = 128; m > 0; m >>= 1) {
        if (threadIdx.x < m) sred[threadIdx.x] += sred[threadIdx.x + m];
        __syncthreads();
    }
    if (threadIdx.x == 0) g_part[blockIdx.x] = sred[0];
}

// deterministic parallel finalize: fixed-shape tree reduction in double
__global__ void vq_finalize_kernel(float* __restrict__ out, int write_loss)
{
    __shared__ double sred[256];
    double s = 0.0;
#pragma unroll
    for (int i = 0; i < 8; ++i) s += g_part[threadIdx.x + i * 256];
    sred[threadIdx.x] = s;
    __syncthreads();
#pragma unroll
    for (int m = 128; m > 0; m >>= 1) {
        if (threadIdx.x < m) sred[threadIdx.x] += sred[threadIdx.x + m];
        __syncthreads();
    }
    if (threadIdx.x == 0 && write_loss) {
        float mmean = (float)(sred[0] / ((double)NROWS * (double)DDIM));
        out[(size_t)NROWS * DDIM] = mmean + 0.25f * mmean;
    }
}

// ---------------------------------------------------------------------------
extern "C" void kernel_launch(void* const* d_in, const int* in_sizes, int n_in,
                              void* d_out, int out_size)
{
    const float* x   = (const float*)d_in[0];
    const float* emb = (const float*)d_in[1];
    if (n_in >= 2 && in_sizes[0] == KCODES * DDIM && in_sizes[1] == NROWS * DDIM) {
        const float* t = x; x = emb; emb = t;
    }
    float* out = (float*)d_out;

    cudaFuncSetAttribute(vq_stage1, cudaFuncAttributeMaxDynamicSharedMemorySize, SM1_BYTES);

    vq_sqnorm_kernel<<<(NROWS * 32) / 256, 256>>>(x,   NROWS,  0);
    vq_sqnorm_kernel<<<(KCODES * 32) / 256, 256>>>(emb, KCODES, 1);
    vq_stage1<<<NROWS / MT, 256, SM1_BYTES>>>(x, emb);
    vq_refine<<<NROWS / 8, 256>>>(x, emb);
    vq_gather_kernel<<<2048, 256>>>(x, emb, out);
    vq_finalize_kernel<<<1, 256>>>(out, out_size > NROWS * DDIM ? 1 : 0);
}